// round 7
// baseline (speedup 1.0000x reference)
#include <cuda_runtime.h>
#include <cstdint>

// Sliding-window attention, B=1,H=16,S=4096,D=64, half-window 256, fp32 I/O.
// Round 7: fp16 m16n8k16 flash attention, P-in-registers (C-frag == A-frag),
// base-2 softmax with scale folded into Q, warp-uniform band fast paths,
// double-buffered K/V with register prefetch and ONE barrier per tile.

#define SEQ    4096
#define NH     16
#define HD     64
#define WHALF  256
#define BQ     128
#define BK     64
#define QSCALE 0.1803368801f       // 0.125 * log2(e)
#define ROWW   36                  // uint32 words per smem row (144 B)

// SMEM word offsets: two K/V buffers; Q staging aliases buffer 1.
#define KB0 0
#define VB0 (64 * ROWW)
#define KB1 (128 * ROWW)
#define VB1 (192 * ROWW)
#define QSTAGE KB1                 // 128 rows x ROWW = buf1 region, transient
#define SMEM_WORDS (256 * ROWW)
#define SMEM_BYTES (SMEM_WORDS * 4)   // 36864 B

static __device__ __forceinline__ uint32_t pack_f16x2(float lo, float hi) {
    uint32_t r;
    asm("cvt.rn.f16x2.f32 %0, %1, %2;" : "=r"(r) : "f"(hi), "f"(lo));
    return r;
}
static __device__ __forceinline__ float ex2f(float x) {
    float r; asm("ex2.approx.f32 %0, %1;" : "=f"(r) : "f"(x)); return r;
}
static __device__ __forceinline__ void mma_f16(float* c, const uint32_t* a,
                                               uint32_t b0, uint32_t b1) {
    asm volatile(
        "mma.sync.aligned.m16n8k16.row.col.f32.f16.f16.f32 "
        "{%0,%1,%2,%3}, {%4,%5,%6,%7}, {%8,%9}, {%0,%1,%2,%3};"
        : "+f"(c[0]), "+f"(c[1]), "+f"(c[2]), "+f"(c[3])
        : "r"(a[0]), "r"(a[1]), "r"(a[2]), "r"(a[3]), "r"(b0), "r"(b1));
}
static __device__ __forceinline__ bool in_band(int qi, int kj) {
    return (unsigned)(qi - kj + WHALF) <= (unsigned)(2 * WHALF);
}

__global__ __launch_bounds__(256, 2)
void swa_h16db_kernel(const float* __restrict__ gq, const float* __restrict__ gk,
                      const float* __restrict__ gv, float* __restrict__ gout)
{
    extern __shared__ uint32_t smu[];

    const int tid   = threadIdx.x;
    const int warp  = tid >> 5;
    const int lane  = tid & 31;
    const int group = lane >> 2;
    const int qp    = lane & 3;

    const int q0 = blockIdx.x * BQ;
    const int h  = blockIdx.y;

    const float* qh = gq + (size_t)h * SEQ * HD;
    const float* kh = gk + (size_t)h * SEQ * HD;
    const float* vh = gv + (size_t)h * SEQ * HD;
    float*       oh = gout + (size_t)h * SEQ * HD;

    const int r0  = warp * 16 + group;
    const int r1  = r0 + 8;
    const int qi0 = q0 + r0;
    const int qi1 = q0 + r1;
    const int wlo = q0 + warp * 16;      // warp's query-row span
    const int whi = wlo + 15;

    const int kstart = (q0 - WHALF) > 0 ? (q0 - WHALF) : 0;
    const int kend   = (q0 + BQ + WHALF) < SEQ ? (q0 + BQ + WHALF) : SEQ;

    // ---- prologue: stage Q (scaled, into buf1 region) + K/V tile0 (buf0) ----
    for (int idx = tid; idx < BQ * 16; idx += 256) {
        const int row = idx >> 4, c = (idx & 15) * 4;
        float4 t = *(const float4*)(qh + (size_t)(q0 + row) * HD + c);
        smu[QSTAGE + row * ROWW + (c >> 1)]     = pack_f16x2(t.x * QSCALE, t.y * QSCALE);
        smu[QSTAGE + row * ROWW + (c >> 1) + 1] = pack_f16x2(t.z * QSCALE, t.w * QSCALE);
    }
    #pragma unroll
    for (int i = 0; i < 4; i++) {
        const int idx = tid + i * 256, row = idx >> 4, c = (idx & 15) * 4;
        float4 t = *(const float4*)(kh + (size_t)(kstart + row) * HD + c);
        smu[KB0 + row * ROWW + (c >> 1)]     = pack_f16x2(t.x, t.y);
        smu[KB0 + row * ROWW + (c >> 1) + 1] = pack_f16x2(t.z, t.w);
    }
    #pragma unroll
    for (int i = 0; i < 2; i++) {
        const int idx = tid + i * 256, rp = idx >> 4, c = (idx & 15) * 4;
        float4 a = *(const float4*)(vh + (size_t)(kstart + 2 * rp) * HD + c);
        float4 b = *(const float4*)(vh + (size_t)(kstart + 2 * rp + 1) * HD + c);
        smu[VB0 + (c + 0) * ROWW + rp] = pack_f16x2(a.x, b.x);
        smu[VB0 + (c + 1) * ROWW + rp] = pack_f16x2(a.y, b.y);
        smu[VB0 + (c + 2) * ROWW + rp] = pack_f16x2(a.z, b.z);
        smu[VB0 + (c + 3) * ROWW + rp] = pack_f16x2(a.w, b.w);
    }
    __syncthreads();

    // ---- hoist Q fragments (16 regs, live whole kernel) ----
    uint32_t qf[4][4];
    #pragma unroll
    for (int kc = 0; kc < 4; kc++) {
        const int w0 = kc * 8 + qp;
        qf[kc][0] = smu[QSTAGE + r0 * ROWW + w0];
        qf[kc][1] = smu[QSTAGE + r1 * ROWW + w0];
        qf[kc][2] = smu[QSTAGE + r0 * ROWW + w0 + 4];
        qf[kc][3] = smu[QSTAGE + r1 * ROWW + w0 + 4];
    }
    __syncthreads();   // Q reads done before iter0 overwrites buf1

    float oacc[8][4];
    #pragma unroll
    for (int nt = 0; nt < 8; nt++)
        #pragma unroll
        for (int j = 0; j < 4; j++) oacc[nt][j] = 0.f;
    float mi0 = -1e30f, mi1 = -1e30f, li0 = 0.f, li1 = 0.f;

    int buf = 0;
    for (int k0 = kstart; k0 < kend; k0 += BK, buf ^= 1) {
        const uint32_t* Kc = smu + (buf ? KB1 : KB0);
        const uint32_t* Vc = smu + (buf ? VB1 : VB0);
        uint32_t*       Kn = smu + (buf ? KB0 : KB1);
        uint32_t*       Vn = smu + (buf ? VB0 : VB1);
        const bool hasnext = (k0 + BK) < kend;
        const int  kn0 = k0 + BK;

        // warp-uniform band classification for this tile
        const bool none = (k0 + BK - 1 < wlo - WHALF) || (k0 > whi + WHALF);
        const bool full = (k0 >= whi - WHALF) && (k0 + BK - 1 <= wlo + WHALF);

        // ---- prefetch K(t+1) into regs (latency hidden behind S-MMA) ----
        float4 kr[4];
        if (hasnext) {
            #pragma unroll
            for (int i = 0; i < 4; i++) {
                const int idx = tid + i * 256, row = idx >> 4, c = (idx & 15) * 4;
                kr[i] = *(const float4*)(kh + (size_t)(kn0 + row) * HD + c);
            }
        }

        // ---- S = Q K^T ----
        float sacc[8][4];
        if (!none) {
            #pragma unroll
            for (int nt = 0; nt < 8; nt++)
                #pragma unroll
                for (int j = 0; j < 4; j++) sacc[nt][j] = 0.f;
            #pragma unroll
            for (int kc = 0; kc < 4; kc++) {
                const int w0 = kc * 8 + qp;
                #pragma unroll
                for (int nt = 0; nt < 8; nt++) {
                    const int kv = nt * 8 + group;
                    uint32_t b0 = Kc[kv * ROWW + w0];
                    uint32_t b1 = Kc[kv * ROWW + w0 + 4];
                    mma_f16(sacc[nt], qf[kc], b0, b1);
                }
            }
        }

        // ---- store K(t+1) to idle buffer (frees kr regs) ----
        if (hasnext) {
            #pragma unroll
            for (int i = 0; i < 4; i++) {
                const int idx = tid + i * 256, row = idx >> 4, c = (idx & 15) * 4;
                Kn[row * ROWW + (c >> 1)]     = pack_f16x2(kr[i].x, kr[i].y);
                Kn[row * ROWW + (c >> 1) + 1] = pack_f16x2(kr[i].z, kr[i].w);
            }
        }

        // ---- prefetch V(t+1) into regs (latency hidden behind softmax) ----
        float4 vr0[2], vr1[2];
        if (hasnext) {
            #pragma unroll
            for (int i = 0; i < 2; i++) {
                const int idx = tid + i * 256, rp = idx >> 4, c = (idx & 15) * 4;
                vr0[i] = *(const float4*)(vh + (size_t)(kn0 + 2 * rp) * HD + c);
                vr1[i] = *(const float4*)(vh + (size_t)(kn0 + 2 * rp + 1) * HD + c);
            }
        }

        // ---- softmax (base-2 domain; scale already folded into Q) ----
        uint32_t pw0[8], pw1[8];
        float al0 = 1.f, al1 = 1.f;
        if (!none) {
            float m0 = -1e30f, m1 = -1e30f;
            if (full) {
                #pragma unroll
                for (int nt = 0; nt < 8; nt++) {
                    m0 = fmaxf(m0, fmaxf(sacc[nt][0], sacc[nt][1]));
                    m1 = fmaxf(m1, fmaxf(sacc[nt][2], sacc[nt][3]));
                }
            } else {
                #pragma unroll
                for (int nt = 0; nt < 8; nt++) {
                    const int kj = k0 + nt * 8 + 2 * qp;
                    if (in_band(qi0, kj)     && sacc[nt][0] > m0) m0 = sacc[nt][0];
                    if (in_band(qi0, kj + 1) && sacc[nt][1] > m0) m0 = sacc[nt][1];
                    if (in_band(qi1, kj)     && sacc[nt][2] > m1) m1 = sacc[nt][2];
                    if (in_band(qi1, kj + 1) && sacc[nt][3] > m1) m1 = sacc[nt][3];
                }
            }
            m0 = fmaxf(m0, __shfl_xor_sync(0xffffffffu, m0, 1));
            m0 = fmaxf(m0, __shfl_xor_sync(0xffffffffu, m0, 2));
            m1 = fmaxf(m1, __shfl_xor_sync(0xffffffffu, m1, 1));
            m1 = fmaxf(m1, __shfl_xor_sync(0xffffffffu, m1, 2));

            const float mn0 = fmaxf(mi0, m0), mn1 = fmaxf(mi1, m1);
            al0 = ex2f(mi0 - mn0); al1 = ex2f(mi1 - mn1);
            mi0 = mn0; mi1 = mn1;

            float rs0 = 0.f, rs1 = 0.f;
            if (full) {
                #pragma unroll
                for (int nt = 0; nt < 8; nt++) {
                    const float p00 = ex2f(sacc[nt][0] - mn0);
                    const float p01 = ex2f(sacc[nt][1] - mn0);
                    const float p10 = ex2f(sacc[nt][2] - mn1);
                    const float p11 = ex2f(sacc[nt][3] - mn1);
                    rs0 += p00 + p01; rs1 += p10 + p11;
                    pw0[nt] = pack_f16x2(p00, p01);
                    pw1[nt] = pack_f16x2(p10, p11);
                }
            } else {
                #pragma unroll
                for (int nt = 0; nt < 8; nt++) {
                    const int kj = k0 + nt * 8 + 2 * qp;
                    const float p00 = in_band(qi0, kj)     ? ex2f(sacc[nt][0] - mn0) : 0.f;
                    const float p01 = in_band(qi0, kj + 1) ? ex2f(sacc[nt][1] - mn0) : 0.f;
                    const float p10 = in_band(qi1, kj)     ? ex2f(sacc[nt][2] - mn1) : 0.f;
                    const float p11 = in_band(qi1, kj + 1) ? ex2f(sacc[nt][3] - mn1) : 0.f;
                    rs0 += p00 + p01; rs1 += p10 + p11;
                    pw0[nt] = pack_f16x2(p00, p01);
                    pw1[nt] = pack_f16x2(p10, p11);
                }
            }
            rs0 += __shfl_xor_sync(0xffffffffu, rs0, 1);
            rs0 += __shfl_xor_sync(0xffffffffu, rs0, 2);
            rs1 += __shfl_xor_sync(0xffffffffu, rs1, 1);
            rs1 += __shfl_xor_sync(0xffffffffu, rs1, 2);
            li0 = li0 * al0 + rs0;
            li1 = li1 * al1 + rs1;

            #pragma unroll
            for (int nt = 0; nt < 8; nt++) {
                oacc[nt][0] *= al0; oacc[nt][1] *= al0;
                oacc[nt][2] *= al1; oacc[nt][3] *= al1;
            }
        }

        // ---- store V(t+1) to idle buffer ----
        if (hasnext) {
            #pragma unroll
            for (int i = 0; i < 2; i++) {
                const int idx = tid + i * 256, rp = idx >> 4, c = (idx & 15) * 4;
                Vn[(c + 0) * ROWW + rp] = pack_f16x2(vr0[i].x, vr1[i].x);
                Vn[(c + 1) * ROWW + rp] = pack_f16x2(vr0[i].y, vr1[i].y);
                Vn[(c + 2) * ROWW + rp] = pack_f16x2(vr0[i].z, vr1[i].z);
                Vn[(c + 3) * ROWW + rp] = pack_f16x2(vr0[i].w, vr1[i].w);
            }
        }

        // ---- O += P V (P fragments straight from registers) ----
        if (!none) {
            #pragma unroll
            for (int kc = 0; kc < 4; kc++) {
                const int w0 = kc * 8 + qp;
                uint32_t aP[4];
                aP[0] = pw0[2 * kc];
                aP[1] = pw1[2 * kc];
                aP[2] = pw0[2 * kc + 1];
                aP[3] = pw1[2 * kc + 1];
                #pragma unroll
                for (int nt = 0; nt < 8; nt++) {
                    const int d = nt * 8 + group;
                    uint32_t b0 = Vc[d * ROWW + w0];
                    uint32_t b1 = Vc[d * ROWW + w0 + 4];
                    mma_f16(oacc[nt], aP, b0, b1);
                }
            }
        }

        __syncthreads();   // readers of current buf done before next iter's STS
    }

    // ---- epilogue ----
    const float inv0 = 1.f / li0;
    const float inv1 = 1.f / li1;
    #pragma unroll
    for (int nt = 0; nt < 8; nt++) {
        const int c = nt * 8 + 2 * qp;
        *(float2*)(oh + (size_t)qi0 * HD + c) = make_float2(oacc[nt][0] * inv0, oacc[nt][1] * inv0);
        *(float2*)(oh + (size_t)qi1 * HD + c) = make_float2(oacc[nt][2] * inv1, oacc[nt][3] * inv1);
    }
}

extern "C" void kernel_launch(void* const* d_in, const int* in_sizes, int n_in,
                              void* d_out, int out_size)
{
    const float* q = (const float*)d_in[0];
    const float* k = (const float*)d_in[1];
    const float* v = (const float*)d_in[2];
    float* out = (float*)d_out;
    (void)in_sizes; (void)n_in; (void)out_size;

    cudaFuncSetAttribute(swa_h16db_kernel, cudaFuncAttributeMaxDynamicSharedMemorySize,
                         SMEM_BYTES);
    dim3 grid(SEQ / BQ, NH);
    swa_h16db_kernel<<<grid, 256, SMEM_BYTES>>>(q, k, v, out);
}

// round 8
// speedup vs baseline: 1.2367x; 1.2367x over previous
#include <cuda_runtime.h>
#include <cstdint>

// Sliding-window attention, B=1,H=16,S=4096,D=64, half-window 256, fp32 I/O.
// Round 8: merge of R6 (simple single-buffer loop, issued well) with R7's
// proven-cheap improvements only: P-in-registers (C-frag==A-frag), base-2
// softmax with scale folded into Q, warp-uniform band fast paths. No register
// prefetch / double buffer (R7 showed it spills at the 128-reg cap).
// CTA = 256 thr (8 warps), BQ=128, BK=64; warp owns 16 query rows.

#define SEQ    4096
#define NH     16
#define HD     64
#define WHALF  256
#define BQ     128
#define BK     64
#define QSCALE 0.1803368801f       // 0.125 * log2(e)
#define ROWW   36                  // uint32 words per smem row (144 B)

// SMEM word offsets. Q staging aliases the K+Vt region (released after hoist).
#define K_OFF  0                   // Ks [64][ROWW]
#define VT_OFF (64 * ROWW)         // Vt [64][ROWW]  (V transposed: [d][kv])
#define QSTAGE 0                   // Qs [128][ROWW] transient
#define SMEM_WORDS (128 * ROWW)
#define SMEM_BYTES (SMEM_WORDS * 4)   // 18432 B

static __device__ __forceinline__ uint32_t pack_f16x2(float lo, float hi) {
    uint32_t r;
    asm("cvt.rn.f16x2.f32 %0, %1, %2;" : "=r"(r) : "f"(hi), "f"(lo));
    return r;
}
static __device__ __forceinline__ float ex2f(float x) {
    float r; asm("ex2.approx.f32 %0, %1;" : "=f"(r) : "f"(x)); return r;
}
static __device__ __forceinline__ void mma_f16(float* c, const uint32_t* a,
                                               uint32_t b0, uint32_t b1) {
    asm volatile(
        "mma.sync.aligned.m16n8k16.row.col.f32.f16.f16.f32 "
        "{%0,%1,%2,%3}, {%4,%5,%6,%7}, {%8,%9}, {%0,%1,%2,%3};"
        : "+f"(c[0]), "+f"(c[1]), "+f"(c[2]), "+f"(c[3])
        : "r"(a[0]), "r"(a[1]), "r"(a[2]), "r"(a[3]), "r"(b0), "r"(b1));
}
static __device__ __forceinline__ bool in_band(int qi, int kj) {
    return (unsigned)(qi - kj + WHALF) <= (unsigned)(2 * WHALF);
}

__global__ __launch_bounds__(256, 2)
void swa_h16r_kernel(const float* __restrict__ gq, const float* __restrict__ gk,
                     const float* __restrict__ gv, float* __restrict__ gout)
{
    extern __shared__ uint32_t smu[];
    uint32_t* KsU = smu + K_OFF;
    uint32_t* VtU = smu + VT_OFF;

    const int tid   = threadIdx.x;
    const int warp  = tid >> 5;
    const int lane  = tid & 31;
    const int group = lane >> 2;
    const int qp    = lane & 3;

    const int q0 = blockIdx.x * BQ;
    const int h  = blockIdx.y;

    const float* qh = gq + (size_t)h * SEQ * HD;
    const float* kh = gk + (size_t)h * SEQ * HD;
    const float* vh = gv + (size_t)h * SEQ * HD;
    float*       oh = gout + (size_t)h * SEQ * HD;

    const int r0  = warp * 16 + group;
    const int r1  = r0 + 8;
    const int qi0 = q0 + r0;
    const int qi1 = q0 + r1;
    const int wlo = q0 + warp * 16;      // warp's query-row span
    const int whi = wlo + 15;

    // ---- stage Q (scaled) into transient smem, hoist fragments ----
    for (int idx = tid; idx < BQ * 16; idx += 256) {
        const int row = idx >> 4, c = (idx & 15) * 4;
        float4 t = *(const float4*)(qh + (size_t)(q0 + row) * HD + c);
        smu[QSTAGE + row * ROWW + (c >> 1)]     = pack_f16x2(t.x * QSCALE, t.y * QSCALE);
        smu[QSTAGE + row * ROWW + (c >> 1) + 1] = pack_f16x2(t.z * QSCALE, t.w * QSCALE);
    }
    __syncthreads();

    uint32_t qf[4][4];
    #pragma unroll
    for (int kc = 0; kc < 4; kc++) {
        const int w0 = kc * 8 + qp;
        qf[kc][0] = smu[QSTAGE + r0 * ROWW + w0];
        qf[kc][1] = smu[QSTAGE + r1 * ROWW + w0];
        qf[kc][2] = smu[QSTAGE + r0 * ROWW + w0 + 4];
        qf[kc][3] = smu[QSTAGE + r1 * ROWW + w0 + 4];
    }

    float oacc[8][4];
    #pragma unroll
    for (int nt = 0; nt < 8; nt++)
        #pragma unroll
        for (int j = 0; j < 4; j++) oacc[nt][j] = 0.f;
    float mi0 = -1e30f, mi1 = -1e30f, li0 = 0.f, li1 = 0.f;

    const int kstart = (q0 - WHALF) > 0 ? (q0 - WHALF) : 0;
    const int kend   = (q0 + BQ + WHALF) < SEQ ? (q0 + BQ + WHALF) : SEQ;

    for (int k0 = kstart; k0 < kend; k0 += BK) {
        __syncthreads();   // previous tile's readers done (also releases Q stage)

        // ---- stage K tile (row-major) + V transposed [d][kv] ----
        for (int idx = tid; idx < BK * 16; idx += 256) {
            const int row = idx >> 4, c = (idx & 15) * 4;
            float4 t = *(const float4*)(kh + (size_t)(k0 + row) * HD + c);
            KsU[row * ROWW + (c >> 1)]     = pack_f16x2(t.x, t.y);
            KsU[row * ROWW + (c >> 1) + 1] = pack_f16x2(t.z, t.w);
        }
        for (int idx = tid; idx < 32 * 16; idx += 256) {
            const int rp = idx >> 4, c = (idx & 15) * 4;
            float4 a = *(const float4*)(vh + (size_t)(k0 + 2 * rp) * HD + c);
            float4 b = *(const float4*)(vh + (size_t)(k0 + 2 * rp + 1) * HD + c);
            VtU[(c + 0) * ROWW + rp] = pack_f16x2(a.x, b.x);
            VtU[(c + 1) * ROWW + rp] = pack_f16x2(a.y, b.y);
            VtU[(c + 2) * ROWW + rp] = pack_f16x2(a.z, b.z);
            VtU[(c + 3) * ROWW + rp] = pack_f16x2(a.w, b.w);
        }
        __syncthreads();

        // warp-uniform band classification
        const bool none = (k0 + BK - 1 < wlo - WHALF) || (k0 > whi + WHALF);
        if (none) continue;
        const bool full = (k0 >= whi - WHALF) && (k0 + BK - 1 <= wlo + WHALF);

        // ---- S = Q K^T : 4 k16-chunks x 8 kv-tiles ----
        float sacc[8][4];
        #pragma unroll
        for (int nt = 0; nt < 8; nt++)
            #pragma unroll
            for (int j = 0; j < 4; j++) sacc[nt][j] = 0.f;
        #pragma unroll
        for (int kc = 0; kc < 4; kc++) {
            const int w0 = kc * 8 + qp;
            #pragma unroll
            for (int nt = 0; nt < 8; nt++) {
                const int kv = nt * 8 + group;
                uint32_t b0 = KsU[kv * ROWW + w0];
                uint32_t b1 = KsU[kv * ROWW + w0 + 4];
                mma_f16(sacc[nt], qf[kc], b0, b1);
            }
        }

        // ---- base-2 softmax (scale pre-folded into Q) ----
        float m0 = -1e30f, m1 = -1e30f;
        if (full) {
            #pragma unroll
            for (int nt = 0; nt < 8; nt++) {
                m0 = fmaxf(m0, fmaxf(sacc[nt][0], sacc[nt][1]));
                m1 = fmaxf(m1, fmaxf(sacc[nt][2], sacc[nt][3]));
            }
        } else {
            #pragma unroll
            for (int nt = 0; nt < 8; nt++) {
                const int kj = k0 + nt * 8 + 2 * qp;
                if (in_band(qi0, kj)     && sacc[nt][0] > m0) m0 = sacc[nt][0];
                if (in_band(qi0, kj + 1) && sacc[nt][1] > m0) m0 = sacc[nt][1];
                if (in_band(qi1, kj)     && sacc[nt][2] > m1) m1 = sacc[nt][2];
                if (in_band(qi1, kj + 1) && sacc[nt][3] > m1) m1 = sacc[nt][3];
            }
        }
        m0 = fmaxf(m0, __shfl_xor_sync(0xffffffffu, m0, 1));
        m0 = fmaxf(m0, __shfl_xor_sync(0xffffffffu, m0, 2));
        m1 = fmaxf(m1, __shfl_xor_sync(0xffffffffu, m1, 1));
        m1 = fmaxf(m1, __shfl_xor_sync(0xffffffffu, m1, 2));

        const float mn0 = fmaxf(mi0, m0), mn1 = fmaxf(mi1, m1);
        const float al0 = ex2f(mi0 - mn0), al1 = ex2f(mi1 - mn1);
        mi0 = mn0; mi1 = mn1;

        // ---- exp + mask, P packed straight into A-fragment registers ----
        uint32_t pw0[8], pw1[8];
        float rs0 = 0.f, rs1 = 0.f;
        if (full) {
            #pragma unroll
            for (int nt = 0; nt < 8; nt++) {
                const float p00 = ex2f(sacc[nt][0] - mn0);
                const float p01 = ex2f(sacc[nt][1] - mn0);
                const float p10 = ex2f(sacc[nt][2] - mn1);
                const float p11 = ex2f(sacc[nt][3] - mn1);
                rs0 += p00 + p01; rs1 += p10 + p11;
                pw0[nt] = pack_f16x2(p00, p01);
                pw1[nt] = pack_f16x2(p10, p11);
            }
        } else {
            #pragma unroll
            for (int nt = 0; nt < 8; nt++) {
                const int kj = k0 + nt * 8 + 2 * qp;
                const float p00 = in_band(qi0, kj)     ? ex2f(sacc[nt][0] - mn0) : 0.f;
                const float p01 = in_band(qi0, kj + 1) ? ex2f(sacc[nt][1] - mn0) : 0.f;
                const float p10 = in_band(qi1, kj)     ? ex2f(sacc[nt][2] - mn1) : 0.f;
                const float p11 = in_band(qi1, kj + 1) ? ex2f(sacc[nt][3] - mn1) : 0.f;
                rs0 += p00 + p01; rs1 += p10 + p11;
                pw0[nt] = pack_f16x2(p00, p01);
                pw1[nt] = pack_f16x2(p10, p11);
            }
        }
        rs0 += __shfl_xor_sync(0xffffffffu, rs0, 1);
        rs0 += __shfl_xor_sync(0xffffffffu, rs0, 2);
        rs1 += __shfl_xor_sync(0xffffffffu, rs1, 1);
        rs1 += __shfl_xor_sync(0xffffffffu, rs1, 2);
        li0 = li0 * al0 + rs0;
        li1 = li1 * al1 + rs1;

        #pragma unroll
        for (int nt = 0; nt < 8; nt++) {
            oacc[nt][0] *= al0; oacc[nt][1] *= al0;
            oacc[nt][2] *= al1; oacc[nt][3] *= al1;
        }

        // ---- O += P V : A-fragments direct from pw registers ----
        #pragma unroll
        for (int kc = 0; kc < 4; kc++) {
            const int w0 = kc * 8 + qp;
            uint32_t aP[4];
            aP[0] = pw0[2 * kc];
            aP[1] = pw1[2 * kc];
            aP[2] = pw0[2 * kc + 1];
            aP[3] = pw1[2 * kc + 1];
            #pragma unroll
            for (int nt = 0; nt < 8; nt++) {
                const int d = nt * 8 + group;
                uint32_t b0 = VtU[d * ROWW + w0];
                uint32_t b1 = VtU[d * ROWW + w0 + 4];
                mma_f16(oacc[nt], aP, b0, b1);
            }
        }
    }

    // ---- epilogue ----
    const float inv0 = 1.f / li0;
    const float inv1 = 1.f / li1;
    #pragma unroll
    for (int nt = 0; nt < 8; nt++) {
        const int c = nt * 8 + 2 * qp;
        *(float2*)(oh + (size_t)qi0 * HD + c) = make_float2(oacc[nt][0] * inv0, oacc[nt][1] * inv0);
        *(float2*)(oh + (size_t)qi1 * HD + c) = make_float2(oacc[nt][2] * inv1, oacc[nt][3] * inv1);
    }
}

extern "C" void kernel_launch(void* const* d_in, const int* in_sizes, int n_in,
                              void* d_out, int out_size)
{
    const float* q = (const float*)d_in[0];
    const float* k = (const float*)d_in[1];
    const float* v = (const float*)d_in[2];
    float* out = (float*)d_out;
    (void)in_sizes; (void)n_in; (void)out_size;

    cudaFuncSetAttribute(swa_h16r_kernel, cudaFuncAttributeMaxDynamicSharedMemorySize,
                         SMEM_BYTES);
    dim3 grid(SEQ / BQ, NH);
    swa_h16r_kernel<<<grid, 256, SMEM_BYTES>>>(q, k, v, out);
}

// round 9
// speedup vs baseline: 1.2968x; 1.0486x over previous
#include <cuda_runtime.h>
#include <cstdint>

// Sliding-window attention, B=1,H=16,S=4096,D=64, half-window 256, fp32 I/O.
// Round 9: R8 compute core + cp.async double-buffered fp32 staging with an
// in-smem f32->f16 convert pass. Staging LDG latency is fully overlapped with
// the previous tile's compute; no register-prefetch pressure (R7's mistake).
// CTA = 256 thr (8 warps), BQ=128, BK=64; warp owns 16 query rows.

#define SEQ    4096
#define NH     16
#define HD     64
#define WHALF  256
#define BQ     128
#define BK     64
#define QSCALE 0.1803368801f       // 0.125 * log2(e)
#define ROWW   36                  // f16 buf: uint32 words per row (144 B)
#define SPITCH 68                  // staging: floats per row (272 B)

// SMEM word offsets (uint32 units)
#define S0K  0                     // staging buf0: K fp32 [64][SPITCH]
#define S0V  4352                  // staging buf0: V fp32 [64][SPITCH]
#define S1K  8704                  // staging buf1: K
#define S1V  13056                 // staging buf1: V
#define KF16 17408                 // Ks f16 [64][ROWW]
#define VF16 19712                 // Vt f16 [64][ROWW] (V transposed [d][kv])
#define QSTAGE S1K                 // Q staging aliases buf1 (transient)
#define SMEM_WORDS 22016
#define SMEM_BYTES (SMEM_WORDS * 4)   // 88064 B

static __device__ __forceinline__ uint32_t smem_u32(const void* p) {
    uint32_t a;
    asm("{ .reg .u64 t; cvta.to.shared.u64 t, %1; cvt.u32.u64 %0, t; }" : "=r"(a) : "l"(p));
    return a;
}
static __device__ __forceinline__ void cp16(uint32_t dst, const void* src) {
    asm volatile("cp.async.cg.shared.global [%0], [%1], 16;" :: "r"(dst), "l"(src));
}
static __device__ __forceinline__ void cp_commit() {
    asm volatile("cp.async.commit_group;" ::: "memory");
}
static __device__ __forceinline__ void cp_wait1() {
    asm volatile("cp.async.wait_group 1;" ::: "memory");
}
static __device__ __forceinline__ void cp_wait0() {
    asm volatile("cp.async.wait_group 0;" ::: "memory");
}
static __device__ __forceinline__ uint32_t pack_f16x2(float lo, float hi) {
    uint32_t r;
    asm("cvt.rn.f16x2.f32 %0, %1, %2;" : "=r"(r) : "f"(hi), "f"(lo));
    return r;
}
static __device__ __forceinline__ float ex2f(float x) {
    float r; asm("ex2.approx.f32 %0, %1;" : "=f"(r) : "f"(x)); return r;
}
static __device__ __forceinline__ void mma_f16(float* c, const uint32_t* a,
                                               uint32_t b0, uint32_t b1) {
    asm volatile(
        "mma.sync.aligned.m16n8k16.row.col.f32.f16.f16.f32 "
        "{%0,%1,%2,%3}, {%4,%5,%6,%7}, {%8,%9}, {%0,%1,%2,%3};"
        : "+f"(c[0]), "+f"(c[1]), "+f"(c[2]), "+f"(c[3])
        : "r"(a[0]), "r"(a[1]), "r"(a[2]), "r"(a[3]), "r"(b0), "r"(b1));
}
static __device__ __forceinline__ bool in_band(int qi, int kj) {
    return (unsigned)(qi - kj + WHALF) <= (unsigned)(2 * WHALF);
}

__global__ __launch_bounds__(256, 2)
void swa_h16cp_kernel(const float* __restrict__ gq, const float* __restrict__ gk,
                      const float* __restrict__ gv, float* __restrict__ gout)
{
    extern __shared__ uint32_t smu[];
    float* smf = (float*)smu;
    const uint32_t sb = smem_u32(smu);
    uint32_t* KsU = smu + KF16;
    uint32_t* VtU = smu + VF16;

    const int tid   = threadIdx.x;
    const int warp  = tid >> 5;
    const int lane  = tid & 31;
    const int group = lane >> 2;
    const int qp    = lane & 3;

    const int q0 = blockIdx.x * BQ;
    const int h  = blockIdx.y;

    const float* qh = gq + (size_t)h * SEQ * HD;
    const float* kh = gk + (size_t)h * SEQ * HD;
    const float* vh = gv + (size_t)h * SEQ * HD;
    float*       oh = gout + (size_t)h * SEQ * HD;

    const int r0  = warp * 16 + group;
    const int r1  = r0 + 8;
    const int qi0 = q0 + r0;
    const int qi1 = q0 + r1;
    const int wlo = q0 + warp * 16;
    const int whi = wlo + 15;

    const int kstart = (q0 - WHALF) > 0 ? (q0 - WHALF) : 0;
    const int kend   = (q0 + BQ + WHALF) < SEQ ? (q0 + BQ + WHALF) : SEQ;

    // per-thread staging coordinates (4 x 16B chunks each for K and V)
    const int srow = tid >> 4;          // rows srow, srow+16, +32, +48
    const int sc16 = tid & 15;          // 16B chunk within 256B row

    // ---- prologue: async-load tile0 into buf0; stage Q into buf1 region ----
    #pragma unroll
    for (int i = 0; i < 4; i++) {
        const int row = srow + i * 16;
        cp16(sb + (S0K + row * SPITCH) * 4 + sc16 * 16,
             kh + (size_t)(kstart + row) * HD + sc16 * 4);
        cp16(sb + (S0V + row * SPITCH) * 4 + sc16 * 16,
             vh + (size_t)(kstart + row) * HD + sc16 * 4);
    }
    cp_commit();

    for (int idx = tid; idx < BQ * 16; idx += 256) {
        const int row = idx >> 4, c = (idx & 15) * 4;
        float4 t = *(const float4*)(qh + (size_t)(q0 + row) * HD + c);
        smu[QSTAGE + row * ROWW + (c >> 1)]     = pack_f16x2(t.x * QSCALE, t.y * QSCALE);
        smu[QSTAGE + row * ROWW + (c >> 1) + 1] = pack_f16x2(t.z * QSCALE, t.w * QSCALE);
    }
    __syncthreads();

    uint32_t qf[4][4];
    #pragma unroll
    for (int kc = 0; kc < 4; kc++) {
        const int w0 = kc * 8 + qp;
        qf[kc][0] = smu[QSTAGE + r0 * ROWW + w0];
        qf[kc][1] = smu[QSTAGE + r1 * ROWW + w0];
        qf[kc][2] = smu[QSTAGE + r0 * ROWW + w0 + 4];
        qf[kc][3] = smu[QSTAGE + r1 * ROWW + w0 + 4];
    }
    __syncthreads();   // qf hoisted before buf1 is overwritten by tile1's cp.async

    float oacc[8][4];
    #pragma unroll
    for (int nt = 0; nt < 8; nt++)
        #pragma unroll
        for (int j = 0; j < 4; j++) oacc[nt][j] = 0.f;
    float mi0 = -1e30f, mi1 = -1e30f, li0 = 0.f, li1 = 0.f;

    int buf = 0;
    for (int k0 = kstart; k0 < kend; k0 += BK, buf ^= 1) {
        const int sk = buf ? S1K : S0K;
        const int sv = buf ? S1V : S0V;
        const bool hasnext = (k0 + BK) < kend;

        // ---- issue tile t+1 into the other staging buffer, then wait tile t ----
        if (hasnext) {
            const int nk = buf ? S0K : S1K;
            const int nv = buf ? S0V : S1V;
            const int kn0 = k0 + BK;
            #pragma unroll
            for (int i = 0; i < 4; i++) {
                const int row = srow + i * 16;
                cp16(sb + (nk + row * SPITCH) * 4 + sc16 * 16,
                     kh + (size_t)(kn0 + row) * HD + sc16 * 4);
                cp16(sb + (nv + row * SPITCH) * 4 + sc16 * 16,
                     vh + (size_t)(kn0 + row) * HD + sc16 * 4);
            }
            cp_commit();
            cp_wait1();
        } else {
            cp_wait0();
        }
        __syncthreads();   // staging(t) visible to all; prev compute done with f16 bufs

        // ---- convert staging fp32 -> f16 Ks (row-major) + Vt (transposed) ----
        #pragma unroll
        for (int i = 0; i < 4; i++) {
            const int idx = tid + i * 256, row = idx >> 4, c = (idx & 15) * 4;
            float4 t = *(const float4*)(smf + sk + row * SPITCH + c);
            KsU[row * ROWW + (c >> 1)]     = pack_f16x2(t.x, t.y);
            KsU[row * ROWW + (c >> 1) + 1] = pack_f16x2(t.z, t.w);
        }
        #pragma unroll
        for (int i = 0; i < 2; i++) {
            const int idx = tid + i * 256, rp = idx >> 4, c = (idx & 15) * 4;
            float4 a = *(const float4*)(smf + sv + (2 * rp) * SPITCH + c);
            float4 b = *(const float4*)(smf + sv + (2 * rp + 1) * SPITCH + c);
            VtU[(c + 0) * ROWW + rp] = pack_f16x2(a.x, b.x);
            VtU[(c + 1) * ROWW + rp] = pack_f16x2(a.y, b.y);
            VtU[(c + 2) * ROWW + rp] = pack_f16x2(a.z, b.z);
            VtU[(c + 3) * ROWW + rp] = pack_f16x2(a.w, b.w);
        }
        __syncthreads();

        // ---- warp-uniform band classification ----
        const bool none = (k0 + BK - 1 < wlo - WHALF) || (k0 > whi + WHALF);
        if (none) continue;
        const bool full = (k0 >= whi - WHALF) && (k0 + BK - 1 <= wlo + WHALF);

        // ---- S = Q K^T ----
        float sacc[8][4];
        #pragma unroll
        for (int nt = 0; nt < 8; nt++)
            #pragma unroll
            for (int j = 0; j < 4; j++) sacc[nt][j] = 0.f;
        #pragma unroll
        for (int kc = 0; kc < 4; kc++) {
            const int w0 = kc * 8 + qp;
            #pragma unroll
            for (int nt = 0; nt < 8; nt++) {
                const int kv = nt * 8 + group;
                uint32_t b0 = KsU[kv * ROWW + w0];
                uint32_t b1 = KsU[kv * ROWW + w0 + 4];
                mma_f16(sacc[nt], qf[kc], b0, b1);
            }
        }

        // ---- base-2 softmax (scale pre-folded into Q) ----
        float m0 = -1e30f, m1 = -1e30f;
        if (full) {
            #pragma unroll
            for (int nt = 0; nt < 8; nt++) {
                m0 = fmaxf(m0, fmaxf(sacc[nt][0], sacc[nt][1]));
                m1 = fmaxf(m1, fmaxf(sacc[nt][2], sacc[nt][3]));
            }
        } else {
            #pragma unroll
            for (int nt = 0; nt < 8; nt++) {
                const int kj = k0 + nt * 8 + 2 * qp;
                if (in_band(qi0, kj)     && sacc[nt][0] > m0) m0 = sacc[nt][0];
                if (in_band(qi0, kj + 1) && sacc[nt][1] > m0) m0 = sacc[nt][1];
                if (in_band(qi1, kj)     && sacc[nt][2] > m1) m1 = sacc[nt][2];
                if (in_band(qi1, kj + 1) && sacc[nt][3] > m1) m1 = sacc[nt][3];
            }
        }
        m0 = fmaxf(m0, __shfl_xor_sync(0xffffffffu, m0, 1));
        m0 = fmaxf(m0, __shfl_xor_sync(0xffffffffu, m0, 2));
        m1 = fmaxf(m1, __shfl_xor_sync(0xffffffffu, m1, 1));
        m1 = fmaxf(m1, __shfl_xor_sync(0xffffffffu, m1, 2));

        const float mn0 = fmaxf(mi0, m0), mn1 = fmaxf(mi1, m1);
        const float al0 = ex2f(mi0 - mn0), al1 = ex2f(mi1 - mn1);
        mi0 = mn0; mi1 = mn1;

        uint32_t pw0[8], pw1[8];
        float rs0 = 0.f, rs1 = 0.f;
        if (full) {
            #pragma unroll
            for (int nt = 0; nt < 8; nt++) {
                const float p00 = ex2f(sacc[nt][0] - mn0);
                const float p01 = ex2f(sacc[nt][1] - mn0);
                const float p10 = ex2f(sacc[nt][2] - mn1);
                const float p11 = ex2f(sacc[nt][3] - mn1);
                rs0 += p00 + p01; rs1 += p10 + p11;
                pw0[nt] = pack_f16x2(p00, p01);
                pw1[nt] = pack_f16x2(p10, p11);
            }
        } else {
            #pragma unroll
            for (int nt = 0; nt < 8; nt++) {
                const int kj = k0 + nt * 8 + 2 * qp;
                const float p00 = in_band(qi0, kj)     ? ex2f(sacc[nt][0] - mn0) : 0.f;
                const float p01 = in_band(qi0, kj + 1) ? ex2f(sacc[nt][1] - mn0) : 0.f;
                const float p10 = in_band(qi1, kj)     ? ex2f(sacc[nt][2] - mn1) : 0.f;
                const float p11 = in_band(qi1, kj + 1) ? ex2f(sacc[nt][3] - mn1) : 0.f;
                rs0 += p00 + p01; rs1 += p10 + p11;
                pw0[nt] = pack_f16x2(p00, p01);
                pw1[nt] = pack_f16x2(p10, p11);
            }
        }
        rs0 += __shfl_xor_sync(0xffffffffu, rs0, 1);
        rs0 += __shfl_xor_sync(0xffffffffu, rs0, 2);
        rs1 += __shfl_xor_sync(0xffffffffu, rs1, 1);
        rs1 += __shfl_xor_sync(0xffffffffu, rs1, 2);
        li0 = li0 * al0 + rs0;
        li1 = li1 * al1 + rs1;

        #pragma unroll
        for (int nt = 0; nt < 8; nt++) {
            oacc[nt][0] *= al0; oacc[nt][1] *= al0;
            oacc[nt][2] *= al1; oacc[nt][3] *= al1;
        }

        // ---- O += P V (A-fragments direct from registers) ----
        #pragma unroll
        for (int kc = 0; kc < 4; kc++) {
            const int w0 = kc * 8 + qp;
            uint32_t aP[4];
            aP[0] = pw0[2 * kc];
            aP[1] = pw1[2 * kc];
            aP[2] = pw0[2 * kc + 1];
            aP[3] = pw1[2 * kc + 1];
            #pragma unroll
            for (int nt = 0; nt < 8; nt++) {
                const int d = nt * 8 + group;
                uint32_t b0 = VtU[d * ROWW + w0];
                uint32_t b1 = VtU[d * ROWW + w0 + 4];
                mma_f16(oacc[nt], aP, b0, b1);
            }
        }
    }

    // ---- epilogue ----
    const float inv0 = 1.f / li0;
    const float inv1 = 1.f / li1;
    #pragma unroll
    for (int nt = 0; nt < 8; nt++) {
        const int c = nt * 8 + 2 * qp;
        *(float2*)(oh + (size_t)qi0 * HD + c) = make_float2(oacc[nt][0] * inv0, oacc[nt][1] * inv0);
        *(float2*)(oh + (size_t)qi1 * HD + c) = make_float2(oacc[nt][2] * inv1, oacc[nt][3] * inv1);
    }
}

extern "C" void kernel_launch(void* const* d_in, const int* in_sizes, int n_in,
                              void* d_out, int out_size)
{
    const float* q = (const float*)d_in[0];
    const float* k = (const float*)d_in[1];
    const float* v = (const float*)d_in[2];
    float* out = (float*)d_out;
    (void)in_sizes; (void)n_in; (void)out_size;

    cudaFuncSetAttribute(swa_h16cp_kernel, cudaFuncAttributeMaxDynamicSharedMemorySize,
                         SMEM_BYTES);
    dim3 grid(SEQ / BQ, NH);
    swa_h16cp_kernel<<<grid, 256, SMEM_BYTES>>>(q, k, v, out);
}

// round 10
// speedup vs baseline: 1.3493x; 1.0405x over previous
#include <cuda_runtime.h>
#include <cstdint>

// Sliding-window attention, B=1,H=16,S=4096,D=64, half-window 256, fp32 I/O.
// Round 10: R9 + ldmatrix.m8n8.x4 fragment loads for K and V (replaces
// 128 LDS.32 + address IMADs per thread-tile with 32 LDSM + uniform adds).
// Ks/Vt are stored rows=n, cols=k, so non-trans ldmatrix gives B-frags direct.
// CTA = 256 thr (8 warps), BQ=128, BK=64; warp owns 16 query rows.

#define SEQ    4096
#define NH     16
#define HD     64
#define WHALF  256
#define BQ     128
#define BK     64
#define QSCALE 0.1803368801f       // 0.125 * log2(e)
#define ROWW   36                  // f16 buf: uint32 words per row (144 B)
#define SPITCH 68                  // staging: floats per row (272 B)

// SMEM word offsets (uint32 units)
#define S0K  0                     // staging buf0: K fp32 [64][SPITCH]
#define S0V  4352
#define S1K  8704
#define S1V  13056
#define KF16 17408                 // Ks f16 [64][ROWW]  rows=kv, cols=d
#define VF16 19712                 // Vt f16 [64][ROWW]  rows=d,  cols=kv
#define QSTAGE S1K                 // Q staging aliases buf1 (transient)
#define SMEM_WORDS 22016
#define SMEM_BYTES (SMEM_WORDS * 4)   // 88064 B

#define NTP_STRIDE (16 * ROWW * 4)    // 2304 B: 16 rows
#define KC_STRIDE  32                 // 8 words: one k16 chunk (low half)

static __device__ __forceinline__ uint32_t smem_u32(const void* p) {
    uint32_t a;
    asm("{ .reg .u64 t; cvta.to.shared.u64 t, %1; cvt.u32.u64 %0, t; }" : "=r"(a) : "l"(p));
    return a;
}
static __device__ __forceinline__ void cp16(uint32_t dst, const void* src) {
    asm volatile("cp.async.cg.shared.global [%0], [%1], 16;" :: "r"(dst), "l"(src));
}
static __device__ __forceinline__ void cp_commit() {
    asm volatile("cp.async.commit_group;" ::: "memory");
}
static __device__ __forceinline__ void cp_wait1() {
    asm volatile("cp.async.wait_group 1;" ::: "memory");
}
static __device__ __forceinline__ void cp_wait0() {
    asm volatile("cp.async.wait_group 0;" ::: "memory");
}
static __device__ __forceinline__ uint32_t pack_f16x2(float lo, float hi) {
    uint32_t r;
    asm("cvt.rn.f16x2.f32 %0, %1, %2;" : "=r"(r) : "f"(hi), "f"(lo));
    return r;
}
static __device__ __forceinline__ float ex2f(float x) {
    float r; asm("ex2.approx.f32 %0, %1;" : "=f"(r) : "f"(x)); return r;
}
static __device__ __forceinline__ void mma_f16(float* c, const uint32_t* a,
                                               uint32_t b0, uint32_t b1) {
    asm volatile(
        "mma.sync.aligned.m16n8k16.row.col.f32.f16.f16.f32 "
        "{%0,%1,%2,%3}, {%4,%5,%6,%7}, {%8,%9}, {%0,%1,%2,%3};"
        : "+f"(c[0]), "+f"(c[1]), "+f"(c[2]), "+f"(c[3])
        : "r"(a[0]), "r"(a[1]), "r"(a[2]), "r"(a[3]), "r"(b0), "r"(b1));
}
static __device__ __forceinline__ void ldsm_x4(uint32_t* d, uint32_t addr) {
    asm volatile(
        "ldmatrix.sync.aligned.m8n8.x4.shared.b16 {%0,%1,%2,%3}, [%4];"
        : "=r"(d[0]), "=r"(d[1]), "=r"(d[2]), "=r"(d[3]) : "r"(addr));
}
static __device__ __forceinline__ bool in_band(int qi, int kj) {
    return (unsigned)(qi - kj + WHALF) <= (unsigned)(2 * WHALF);
}

__global__ __launch_bounds__(256, 2)
void swa_h16lm_kernel(const float* __restrict__ gq, const float* __restrict__ gk,
                      const float* __restrict__ gv, float* __restrict__ gout)
{
    extern __shared__ uint32_t smu[];
    float* smf = (float*)smu;
    const uint32_t sb = smem_u32(smu);
    uint32_t* KsU = smu + KF16;
    uint32_t* VtU = smu + VF16;

    const int tid   = threadIdx.x;
    const int warp  = tid >> 5;
    const int lane  = tid & 31;
    const int group = lane >> 2;
    const int qp    = lane & 3;

    const int q0 = blockIdx.x * BQ;
    const int h  = blockIdx.y;

    const float* qh = gq + (size_t)h * SEQ * HD;
    const float* kh = gk + (size_t)h * SEQ * HD;
    const float* vh = gv + (size_t)h * SEQ * HD;
    float*       oh = gout + (size_t)h * SEQ * HD;

    const int r0  = warp * 16 + group;
    const int r1  = r0 + 8;
    const int qi0 = q0 + r0;
    const int qi1 = q0 + r1;
    const int wlo = q0 + warp * 16;
    const int whi = wlo + 15;

    // per-lane ldmatrix base: matrices (m=l/8): m0=(nt,klo) m1=(nt,khi)
    // m2=(nt+1,klo) m3=(nt+1,khi); row (l>>4)*8 + (l&7), +16B if (l>>3)&1.
    const uint32_t lmoff = (uint32_t)((((lane >> 4) * 8 + (lane & 7)) * ROWW) * 4
                                      + ((lane >> 3) & 1) * 16);
    const uint32_t addrK = sb + KF16 * 4 + lmoff;
    const uint32_t addrV = sb + VF16 * 4 + lmoff;

    const int kstart = (q0 - WHALF) > 0 ? (q0 - WHALF) : 0;
    const int kend   = (q0 + BQ + WHALF) < SEQ ? (q0 + BQ + WHALF) : SEQ;

    // staging coordinates (4 x 16B chunks each for K and V)
    const int srow = tid >> 4;
    const int sc16 = tid & 15;

    // ---- prologue: async-load tile0 into buf0; stage Q into buf1 region ----
    #pragma unroll
    for (int i = 0; i < 4; i++) {
        const int row = srow + i * 16;
        cp16(sb + (S0K + row * SPITCH) * 4 + sc16 * 16,
             kh + (size_t)(kstart + row) * HD + sc16 * 4);
        cp16(sb + (S0V + row * SPITCH) * 4 + sc16 * 16,
             vh + (size_t)(kstart + row) * HD + sc16 * 4);
    }
    cp_commit();

    for (int idx = tid; idx < BQ * 16; idx += 256) {
        const int row = idx >> 4, c = (idx & 15) * 4;
        float4 t = *(const float4*)(qh + (size_t)(q0 + row) * HD + c);
        smu[QSTAGE + row * ROWW + (c >> 1)]     = pack_f16x2(t.x * QSCALE, t.y * QSCALE);
        smu[QSTAGE + row * ROWW + (c >> 1) + 1] = pack_f16x2(t.z * QSCALE, t.w * QSCALE);
    }
    __syncthreads();

    uint32_t qf[4][4];
    #pragma unroll
    for (int kc = 0; kc < 4; kc++) {
        const int w0 = kc * 8 + qp;
        qf[kc][0] = smu[QSTAGE + r0 * ROWW + w0];
        qf[kc][1] = smu[QSTAGE + r1 * ROWW + w0];
        qf[kc][2] = smu[QSTAGE + r0 * ROWW + w0 + 4];
        qf[kc][3] = smu[QSTAGE + r1 * ROWW + w0 + 4];
    }
    __syncthreads();   // qf hoisted before buf1 is overwritten by tile1's cp.async

    float oacc[8][4];
    #pragma unroll
    for (int nt = 0; nt < 8; nt++)
        #pragma unroll
        for (int j = 0; j < 4; j++) oacc[nt][j] = 0.f;
    float mi0 = -1e30f, mi1 = -1e30f, li0 = 0.f, li1 = 0.f;

    int buf = 0;
    for (int k0 = kstart; k0 < kend; k0 += BK, buf ^= 1) {
        const int sk = buf ? S1K : S0K;
        const int sv = buf ? S1V : S0V;
        const bool hasnext = (k0 + BK) < kend;

        // ---- issue tile t+1; wait for tile t ----
        if (hasnext) {
            const int nk = buf ? S0K : S1K;
            const int nv = buf ? S0V : S1V;
            const int kn0 = k0 + BK;
            #pragma unroll
            for (int i = 0; i < 4; i++) {
                const int row = srow + i * 16;
                cp16(sb + (nk + row * SPITCH) * 4 + sc16 * 16,
                     kh + (size_t)(kn0 + row) * HD + sc16 * 4);
                cp16(sb + (nv + row * SPITCH) * 4 + sc16 * 16,
                     vh + (size_t)(kn0 + row) * HD + sc16 * 4);
            }
            cp_commit();
            cp_wait1();
        } else {
            cp_wait0();
        }
        __syncthreads();

        // ---- convert staging fp32 -> f16 Ks (rows=kv) + Vt (rows=d) ----
        #pragma unroll
        for (int i = 0; i < 4; i++) {
            const int idx = tid + i * 256, row = idx >> 4, c = (idx & 15) * 4;
            float4 t = *(const float4*)(smf + sk + row * SPITCH + c);
            KsU[row * ROWW + (c >> 1)]     = pack_f16x2(t.x, t.y);
            KsU[row * ROWW + (c >> 1) + 1] = pack_f16x2(t.z, t.w);
        }
        #pragma unroll
        for (int i = 0; i < 2; i++) {
            const int idx = tid + i * 256, rp = idx >> 4, c = (idx & 15) * 4;
            float4 a = *(const float4*)(smf + sv + (2 * rp) * SPITCH + c);
            float4 b = *(const float4*)(smf + sv + (2 * rp + 1) * SPITCH + c);
            VtU[(c + 0) * ROWW + rp] = pack_f16x2(a.x, b.x);
            VtU[(c + 1) * ROWW + rp] = pack_f16x2(a.y, b.y);
            VtU[(c + 2) * ROWW + rp] = pack_f16x2(a.z, b.z);
            VtU[(c + 3) * ROWW + rp] = pack_f16x2(a.w, b.w);
        }
        __syncthreads();

        // ---- warp-uniform band classification ----
        const bool none = (k0 + BK - 1 < wlo - WHALF) || (k0 > whi + WHALF);
        if (none) continue;
        const bool full = (k0 >= whi - WHALF) && (k0 + BK - 1 <= wlo + WHALF);

        // ---- S = Q K^T : ldmatrix B-frags, 8 nt per kc ----
        float sacc[8][4];
        #pragma unroll
        for (int nt = 0; nt < 8; nt++)
            #pragma unroll
            for (int j = 0; j < 4; j++) sacc[nt][j] = 0.f;
        #pragma unroll
        for (int kc = 0; kc < 4; kc++) {
            uint32_t bk[16];
            #pragma unroll
            for (int ntp = 0; ntp < 4; ntp++)
                ldsm_x4(bk + ntp * 4, addrK + ntp * NTP_STRIDE + kc * KC_STRIDE);
            #pragma unroll
            for (int nt = 0; nt < 8; nt++)
                mma_f16(sacc[nt], qf[kc], bk[(nt >> 1) * 4 + (nt & 1) * 2],
                                          bk[(nt >> 1) * 4 + (nt & 1) * 2 + 1]);
        }

        // ---- base-2 softmax (scale pre-folded into Q) ----
        float m0 = -1e30f, m1 = -1e30f;
        if (full) {
            #pragma unroll
            for (int nt = 0; nt < 8; nt++) {
                m0 = fmaxf(m0, fmaxf(sacc[nt][0], sacc[nt][1]));
                m1 = fmaxf(m1, fmaxf(sacc[nt][2], sacc[nt][3]));
            }
        } else {
            #pragma unroll
            for (int nt = 0; nt < 8; nt++) {
                const int kj = k0 + nt * 8 + 2 * qp;
                if (in_band(qi0, kj)     && sacc[nt][0] > m0) m0 = sacc[nt][0];
                if (in_band(qi0, kj + 1) && sacc[nt][1] > m0) m0 = sacc[nt][1];
                if (in_band(qi1, kj)     && sacc[nt][2] > m1) m1 = sacc[nt][2];
                if (in_band(qi1, kj + 1) && sacc[nt][3] > m1) m1 = sacc[nt][3];
            }
        }
        m0 = fmaxf(m0, __shfl_xor_sync(0xffffffffu, m0, 1));
        m0 = fmaxf(m0, __shfl_xor_sync(0xffffffffu, m0, 2));
        m1 = fmaxf(m1, __shfl_xor_sync(0xffffffffu, m1, 1));
        m1 = fmaxf(m1, __shfl_xor_sync(0xffffffffu, m1, 2));

        const float mn0 = fmaxf(mi0, m0), mn1 = fmaxf(mi1, m1);
        const float al0 = ex2f(mi0 - mn0), al1 = ex2f(mi1 - mn1);
        mi0 = mn0; mi1 = mn1;

        uint32_t pw0[8], pw1[8];
        float rs0 = 0.f, rs1 = 0.f;
        if (full) {
            #pragma unroll
            for (int nt = 0; nt < 8; nt++) {
                const float p00 = ex2f(sacc[nt][0] - mn0);
                const float p01 = ex2f(sacc[nt][1] - mn0);
                const float p10 = ex2f(sacc[nt][2] - mn1);
                const float p11 = ex2f(sacc[nt][3] - mn1);
                rs0 += p00 + p01; rs1 += p10 + p11;
                pw0[nt] = pack_f16x2(p00, p01);
                pw1[nt] = pack_f16x2(p10, p11);
            }
        } else {
            #pragma unroll
            for (int nt = 0; nt < 8; nt++) {
                const int kj = k0 + nt * 8 + 2 * qp;
                const float p00 = in_band(qi0, kj)     ? ex2f(sacc[nt][0] - mn0) : 0.f;
                const float p01 = in_band(qi0, kj + 1) ? ex2f(sacc[nt][1] - mn0) : 0.f;
                const float p10 = in_band(qi1, kj)     ? ex2f(sacc[nt][2] - mn1) : 0.f;
                const float p11 = in_band(qi1, kj + 1) ? ex2f(sacc[nt][3] - mn1) : 0.f;
                rs0 += p00 + p01; rs1 += p10 + p11;
                pw0[nt] = pack_f16x2(p00, p01);
                pw1[nt] = pack_f16x2(p10, p11);
            }
        }
        rs0 += __shfl_xor_sync(0xffffffffu, rs0, 1);
        rs0 += __shfl_xor_sync(0xffffffffu, rs0, 2);
        rs1 += __shfl_xor_sync(0xffffffffu, rs1, 1);
        rs1 += __shfl_xor_sync(0xffffffffu, rs1, 2);
        li0 = li0 * al0 + rs0;
        li1 = li1 * al1 + rs1;

        #pragma unroll
        for (int nt = 0; nt < 8; nt++) {
            oacc[nt][0] *= al0; oacc[nt][1] *= al0;
            oacc[nt][2] *= al1; oacc[nt][3] *= al1;
        }

        // ---- O += P V : ldmatrix B-frags from Vt ----
        #pragma unroll
        for (int kc = 0; kc < 4; kc++) {
            uint32_t bv[16];
            #pragma unroll
            for (int ntp = 0; ntp < 4; ntp++)
                ldsm_x4(bv + ntp * 4, addrV + ntp * NTP_STRIDE + kc * KC_STRIDE);
            uint32_t aP[4];
            aP[0] = pw0[2 * kc];
            aP[1] = pw1[2 * kc];
            aP[2] = pw0[2 * kc + 1];
            aP[3] = pw1[2 * kc + 1];
            #pragma unroll
            for (int nt = 0; nt < 8; nt++)
                mma_f16(oacc[nt], aP, bv[(nt >> 1) * 4 + (nt & 1) * 2],
                                      bv[(nt >> 1) * 4 + (nt & 1) * 2 + 1]);
        }
    }

    // ---- epilogue ----
    const float inv0 = 1.f / li0;
    const float inv1 = 1.f / li1;
    #pragma unroll
    for (int nt = 0; nt < 8; nt++) {
        const int c = nt * 8 + 2 * qp;
        *(float2*)(oh + (size_t)qi0 * HD + c) = make_float2(oacc[nt][0] * inv0, oacc[nt][1] * inv0);
        *(float2*)(oh + (size_t)qi1 * HD + c) = make_float2(oacc[nt][2] * inv1, oacc[nt][3] * inv1);
    }
}

extern "C" void kernel_launch(void* const* d_in, const int* in_sizes, int n_in,
                              void* d_out, int out_size)
{
    const float* q = (const float*)d_in[0];
    const float* k = (const float*)d_in[1];
    const float* v = (const float*)d_in[2];
    float* out = (float*)d_out;
    (void)in_sizes; (void)n_in; (void)out_size;

    cudaFuncSetAttribute(swa_h16lm_kernel, cudaFuncAttributeMaxDynamicSharedMemorySize,
                         SMEM_BYTES);
    dim3 grid(SEQ / BQ, NH);
    swa_h16lm_kernel<<<grid, 256, SMEM_BYTES>>>(q, k, v, out);
}